// round 15
// baseline (speedup 1.0000x reference)
#include <cuda_runtime.h>
#include <cuda_bf16.h>
#include <cstdint>

#define NT 2048
#define CD 768
#define INFF  __int_as_float(0x7f800000)
#define NINFF __int_as_float(0xff800000)
typedef unsigned long long ull;

// ---------------------------------------------------------------------------
__device__ float g_z1n[4 * NT * CD];
__device__ float g_z2n[4 * NT * CD];
__device__ __nv_bfloat16 g_rh[8 * NT * CD];
__device__ __nv_bfloat16 g_rl[8 * NT * CD];
__device__ __nv_bfloat16 g_nh[8 * NT * CD];
__device__ __nv_bfloat16 g_nl[8 * NT * CD];
__device__ float g_sq[8 * NT];
__device__ float g_inv[8 * NT];
__device__ float g_Sself[8ULL * NT * NT];
__device__ ull   g_rowmin[12 * NT];
__device__ ull   g_colmin[12 * NT];
__device__ int   g_neighCB[8 * NT * 5];
__device__ int   g_negCB[8 * NT * 11];     // unmasked top-11 (rank order)
__device__ int   g_neighA[8 * NT * 5];
__device__ int   g_idxB[12 * NT];
__device__ int   g_order[12 * NT];
__device__ int   g_negc[12];
__device__ float g_rowCB[8 * NT];
__device__ float g_rowNRC[12 * NT];
__device__ float g_cntNRC[12 * NT];
__device__ float g_slots[32];

struct Cfg {
    int nU;
    int u_side[12], u_p[12], u_q[12];
    int pi_uslot[12], pi_swap[12];
    int pi_side[12], pi_p[12], pi_q[12];
    unsigned kp[12][2];
    unsigned cbk[8][2];
};

// ---------------------------------------------------------------------------
__host__ __device__ __forceinline__ void threefry2x32(
    uint32_t k0, uint32_t k1, uint32_t c0, uint32_t c1, uint32_t& o0, uint32_t& o1)
{
    uint32_t ks2 = k0 ^ k1 ^ 0x1BD11BDAu;
    uint32_t x0 = c0 + k0, x1 = c1 + k1;
#define TF_R(r) { x0 += x1; x1 = (x1 << (r)) | (x1 >> (32 - (r))); x1 ^= x0; }
    TF_R(13) TF_R(15) TF_R(26) TF_R(6)
    x0 += k1;  x1 += ks2 + 1u;
    TF_R(17) TF_R(29) TF_R(16) TF_R(24)
    x0 += ks2; x1 += k0 + 2u;
    TF_R(13) TF_R(15) TF_R(26) TF_R(6)
    x0 += k0;  x1 += k1 + 3u;
    TF_R(17) TF_R(29) TF_R(16) TF_R(24)
    x0 += k1;  x1 += ks2 + 4u;
    TF_R(13) TF_R(15) TF_R(26) TF_R(6)
    x0 += ks2; x1 += k0 + 5u;
#undef TF_R
    o0 = x0; o1 = x1;
}
__host__ __device__ __forceinline__ uint32_t tf_bits(uint32_t k0, uint32_t k1, uint32_t idx) {
    uint32_t o0, o1;
    threefry2x32(k0, k1, 0u, idx, o0, o1);
    return o0 ^ o1;
}
__device__ __forceinline__ ull packmin(float v, unsigned idx) {
    unsigned u = __float_as_uint(v);
    u = (u & 0x80000000u) ? ~u : (u | 0x80000000u);
    return ((ull)u << 32) | idx;
}
__device__ __forceinline__ ull packnn(float v, unsigned idx) {
    return ((ull)__float_as_uint(v) << 32) | idx;
}

// ---------------------------------------------------------------------------
__global__ void normalize_kernel(const float* __restrict__ z1,
                                 const float* __restrict__ z2) {
    int gw = (blockIdx.x * blockDim.x + threadIdx.x) >> 5;
    int lane = threadIdx.x & 31;
    if (gw >= 8 * NT) return;
    const float* src;
    float* dst;
    if (gw < 4 * NT) { src = z1 + (size_t)gw * CD; dst = g_z1n + (size_t)gw * CD; }
    else { src = z2 + (size_t)(gw - 4 * NT) * CD; dst = g_z2n + (size_t)(gw - 4 * NT) * CD; }
    __nv_bfloat16* rh = g_rh + (size_t)gw * CD;
    __nv_bfloat16* rl = g_rl + (size_t)gw * CD;
    __nv_bfloat16* nh = g_nh + (size_t)gw * CD;
    __nv_bfloat16* nl = g_nl + (size_t)gw * CD;
    float a[24];
    float s = 0.f;
#pragma unroll
    for (int u = 0; u < 24; u++) { float v = src[lane + u * 32]; a[u] = v; s += v * v; }
#pragma unroll
    for (int off = 16; off; off >>= 1) s += __shfl_xor_sync(0xffffffffu, s, off);
    float inv = rsqrtf(s + 1e-12f);
    if (lane == 0) { g_sq[gw] = s; g_inv[gw] = inv; }
#pragma unroll
    for (int u = 0; u < 24; u++) {
        int c = lane + u * 32;
        float x = a[u];
        __nv_bfloat16 h = __float2bfloat16_rn(x);
        rh[c] = h; rl[c] = __float2bfloat16_rn(x - __bfloat162float(h));
        float xn = x * inv;
        dst[c] = xn;
        __nv_bfloat16 hn = __float2bfloat16_rn(xn);
        nh[c] = hn; nl[c] = __float2bfloat16_rn(xn - __bfloat162float(hn));
    }
}

__global__ void init_kernel() {
    int i = blockIdx.x * blockDim.x + threadIdx.x;
    if (i < 12 * NT) { g_rowmin[i] = ~0ull; g_colmin[i] = ~0ull; }
}

// ---------------------------------------------------------------------------
// bf16x3 HMMA GEMM. mode 0: self, symmetric (skip bx<by, mirror via smem).
// mode 1: cross, fused row/col argmin of (1-dot).
// ---------------------------------------------------------------------------
#define STG 40960
__device__ __forceinline__ void mma16816(float* d, const uint32_t* a, const uint32_t* b) {
    asm volatile(
        "mma.sync.aligned.m16n8k16.row.col.f32.bf16.bf16.f32 "
        "{%0,%1,%2,%3}, {%4,%5,%6,%7}, {%8,%9}, {%0,%1,%2,%3};\n"
        : "+f"(d[0]), "+f"(d[1]), "+f"(d[2]), "+f"(d[3])
        : "r"(a[0]), "r"(a[1]), "r"(a[2]), "r"(a[3]), "r"(b[0]), "r"(b[1]));
}
__device__ __forceinline__ void ldsm4(uint32_t* a, uint32_t p) {
    asm volatile("ldmatrix.sync.aligned.m8n8.x4.shared.b16 {%0,%1,%2,%3}, [%4];\n"
                 : "=r"(a[0]), "=r"(a[1]), "=r"(a[2]), "=r"(a[3]) : "r"(p));
}
__device__ __forceinline__ void cpa16(uint32_t dst, const void* src) {
    asm volatile("cp.async.cg.shared.global [%0], [%1], 16;\n" :: "r"(dst), "l"(src) : "memory");
}

__global__ __launch_bounds__(256, 2) void mma_gemm_kernel(
    const __nv_bfloat16* __restrict__ rh, const __nv_bfloat16* __restrict__ rl,
    const __nv_bfloat16* __restrict__ nh, const __nv_bfloat16* __restrict__ nl,
    int mode, Cfg cfg)
{
    if (mode == 0 && blockIdx.x < blockIdx.y) return;
    extern __shared__ char dsm[];
    uint32_t smb;
    asm("{ .reg .u64 t; cvta.to.shared.u64 t, %1; cvt.u32.u64 %0, t; }" : "=r"(smb) : "l"(dsm));
    int tid = threadIdx.x, wid = tid >> 5, lane = tid & 31;
    int z = blockIdx.z;
    const __nv_bfloat16 *Ah, *Al, *Bh, *Bl;
    if (mode == 0) {
        Ah = rh + (size_t)z * NT * CD; Al = rl + (size_t)z * NT * CD;
        Bh = Ah; Bl = Al;
    } else {
        int sd = cfg.u_side[z];
        size_t po = (size_t)(sd * 4 + cfg.u_p[z]) * NT * CD;
        size_t qo = (size_t)((1 - sd) * 4 + cfg.u_q[z]) * NT * CD;
        Ah = nh + po; Al = nl + po; Bh = nh + qo; Bl = nl + qo;
    }
    int rbase = blockIdx.y * 128, cbase = blockIdx.x * 128;

    auto load_stage = [&](int chunk, int st) {
#pragma unroll
        for (int i = 0; i < 8; i++) {
            int id = tid + i * 256;
            int buf = id >> 9, r = (id >> 2) & 127, seg = id & 3;
            const __nv_bfloat16* gp;
            int grow = (buf < 2 ? rbase : cbase) + r;
            gp = (buf == 0 ? Ah : buf == 1 ? Al : buf == 2 ? Bh : Bl)
                 + (size_t)grow * CD + chunk * 32 + seg * 8;
            cpa16(smb + st * STG + buf * 10240 + r * 80 + seg * 16, gp);
        }
        asm volatile("cp.async.commit_group;\n" ::: "memory");
    };

    float acc[4][4][4];
#pragma unroll
    for (int i = 0; i < 4; i++)
#pragma unroll
        for (int j = 0; j < 4; j++)
#pragma unroll
            for (int k = 0; k < 4; k++) acc[i][j][k] = 0.f;

    int wr = wid >> 2, wc = wid & 3;
    int m0 = wr * 64, n0 = wc * 32;

    load_stage(0, 0);
    for (int c = 0; c < 24; c++) {
        int st = c & 1;
        if (c < 23) {
            load_stage(c + 1, st ^ 1);
            asm volatile("cp.async.wait_group 1;\n" ::: "memory");
        } else {
            asm volatile("cp.async.wait_group 0;\n" ::: "memory");
        }
        __syncthreads();
        uint32_t aH = smb + st * STG, aL = aH + 10240;
#pragma unroll
        for (int ks = 0; ks < 2; ks++) {
            uint32_t arow = (uint32_t)((lane & 15)) * 80 + ks * 32 + ((lane >> 4) << 4);
            uint32_t ah[4][4];
#pragma unroll
            for (int mi = 0; mi < 4; mi++)
                ldsm4(ah[mi], aH + (m0 + mi * 16) * 80 + arow);
            uint32_t boff = (uint32_t)(lane >> 2) * 80 + ks * 32 + ((lane & 3) << 2);
            uint32_t bh[4][2], bl[4][2];
#pragma unroll
            for (int nj = 0; nj < 4; nj++) {
                uint32_t o = (n0 + nj * 8) * 80 + boff;
                bh[nj][0] = *(const uint32_t*)(dsm + st * STG + 20480 + o);
                bh[nj][1] = *(const uint32_t*)(dsm + st * STG + 20480 + o + 16);
                bl[nj][0] = *(const uint32_t*)(dsm + st * STG + 30720 + o);
                bl[nj][1] = *(const uint32_t*)(dsm + st * STG + 30720 + o + 16);
            }
#pragma unroll
            for (int mi = 0; mi < 4; mi++)
#pragma unroll
                for (int nj = 0; nj < 4; nj++) {
                    mma16816(acc[mi][nj], ah[mi], bh[nj]);
                    mma16816(acc[mi][nj], ah[mi], bl[nj]);
                }
            uint32_t al[4][4];
#pragma unroll
            for (int mi = 0; mi < 4; mi++)
                ldsm4(al[mi], aL + (m0 + mi * 16) * 80 + arow);
#pragma unroll
            for (int mi = 0; mi < 4; mi++)
#pragma unroll
                for (int nj = 0; nj < 4; nj++)
                    mma16816(acc[mi][nj], al[mi], bh[nj]);
        }
        __syncthreads();
    }

    if (mode == 0) {
        float* S = g_Sself + (size_t)z * NT * NT;
#pragma unroll
        for (int mi = 0; mi < 4; mi++) {
            int row = rbase + m0 + mi * 16 + (lane >> 2);
#pragma unroll
            for (int nj = 0; nj < 4; nj++) {
                int col = cbase + n0 + nj * 8 + 2 * (lane & 3);
                *(float2*)(S + (size_t)row * NT + col) =
                    make_float2(acc[mi][nj][0], acc[mi][nj][1]);
                *(float2*)(S + (size_t)(row + 8) * NT + col) =
                    make_float2(acc[mi][nj][2], acc[mi][nj][3]);
            }
        }
        if (blockIdx.x != blockIdx.y) {
            float* stage = (float*)dsm;
#pragma unroll
            for (int mi = 0; mi < 4; mi++) {
                int rloc = m0 + mi * 16 + (lane >> 2);
#pragma unroll
                for (int nj = 0; nj < 4; nj++) {
                    int cl = n0 + nj * 8 + 2 * (lane & 3);
                    stage[cl * 132 + rloc] = acc[mi][nj][0];
                    stage[(cl + 1) * 132 + rloc] = acc[mi][nj][1];
                    stage[cl * 132 + rloc + 8] = acc[mi][nj][2];
                    stage[(cl + 1) * 132 + rloc + 8] = acc[mi][nj][3];
                }
            }
            __syncthreads();
            for (int rr = 0; rr < 128; rr += 32) {
                int tr = rr + (tid >> 3);
                int off = (tid & 7) * 4;
#pragma unroll
                for (int k = 0; k < 4; k++)
                    *(float4*)(S + (size_t)(cbase + tr) * NT + rbase + off + k * 32) =
                        *(const float4*)(stage + tr * 132 + off + k * 32);
            }
        }
    } else {
        int u = z;
#pragma unroll
        for (int mi = 0; mi < 4; mi++) {
            int row = rbase + m0 + mi * 16 + (lane >> 2);
            ull r0 = ~0ull, r1 = ~0ull;
#pragma unroll
            for (int nj = 0; nj < 4; nj++) {
                int col = cbase + n0 + nj * 8 + 2 * (lane & 3);
                ull k;
                k = packmin(1.f - acc[mi][nj][0], col);     if (k < r0) r0 = k;
                k = packmin(1.f - acc[mi][nj][1], col + 1); if (k < r0) r0 = k;
                k = packmin(1.f - acc[mi][nj][2], col);     if (k < r1) r1 = k;
                k = packmin(1.f - acc[mi][nj][3], col + 1); if (k < r1) r1 = k;
            }
#pragma unroll
            for (int m = 1; m < 4; m <<= 1) {
                ull o0 = __shfl_xor_sync(0xffffffffu, r0, m);
                ull o1 = __shfl_xor_sync(0xffffffffu, r1, m);
                if (o0 < r0) r0 = o0;
                if (o1 < r1) r1 = o1;
            }
            if ((lane & 3) == 0) {
                atomicMin(&g_rowmin[u * NT + row], r0);
                atomicMin(&g_rowmin[u * NT + row + 8], r1);
            }
        }
#pragma unroll
        for (int nj = 0; nj < 4; nj++) {
            int col = cbase + n0 + nj * 8 + 2 * (lane & 3);
            ull c0 = ~0ull, c1 = ~0ull;
#pragma unroll
            for (int mi = 0; mi < 4; mi++) {
                int row = rbase + m0 + mi * 16 + (lane >> 2);
                ull k;
                k = packmin(1.f - acc[mi][nj][0], row);     if (k < c0) c0 = k;
                k = packmin(1.f - acc[mi][nj][2], row + 8); if (k < c0) c0 = k;
                k = packmin(1.f - acc[mi][nj][1], row);     if (k < c1) c1 = k;
                k = packmin(1.f - acc[mi][nj][3], row + 8); if (k < c1) c1 = k;
            }
#pragma unroll
            for (int m = 4; m < 32; m <<= 1) {
                ull o0 = __shfl_xor_sync(0xffffffffu, c0, m);
                ull o1 = __shfl_xor_sync(0xffffffffu, c1, m);
                if (o0 < c0) c0 = o0;
                if (o1 < c1) c1 = o1;
            }
            if ((lane >> 2) == 0) {
                atomicMin(&g_colmin[u * NT + col], c0);
                atomicMin(&g_colmin[u * NT + col + 1], c1);
            }
        }
    }
}

// ---------------------------------------------------------------------------
// Dual-mode self select with float-threshold hot path.
// ---------------------------------------------------------------------------
#define SENTK (((ull)0x7f800000u << 32) | 0xffffffffu)
__global__ void self_select_kernel() {
    __shared__ ull smA[24], smB[24];
    int row = blockIdx.x, s = blockIdx.y;
    int wid = threadIdx.x >> 5, lane = threadIdx.x & 31;
    const float* sqv = g_sq + (size_t)s * NT;
    const float* invv = g_inv + (size_t)s * NT;
    const float* r = g_Sself + (size_t)s * NT * NT + (size_t)row * NT;
    float msq = sqv[row], minv = invv[row];
    ull kA[6], kB[6];
#pragma unroll
    for (int u = 0; u < 6; u++) { kA[u] = SENTK; kB[u] = SENTK; }
    float t5A = INFF, t5B = INFF;

    float4 dd[4], qq[4], ii[4];
#pragma unroll
    for (int it = 0; it < 4; it++) {
        int j0 = wid * 512 + it * 128 + lane * 4;
        dd[it] = *(const float4*)(r + j0);
        qq[it] = *(const float4*)(sqv + j0);
        ii[it] = *(const float4*)(invv + j0);
    }
#pragma unroll
    for (int it = 0; it < 4; it++) {
        int j0 = wid * 512 + it * 128 + lane * 4;
        float d_[4] = {dd[it].x, dd[it].y, dd[it].z, dd[it].w};
        float q_[4] = {qq[it].x, qq[it].y, qq[it].z, qq[it].w};
        float i_[4] = {ii[it].x, ii[it].y, ii[it].z, ii[it].w};
#pragma unroll
        for (int c = 0; c < 4; c++) {
            unsigned j = j0 + c;
            float v0 = fmaxf(msq + q_[c] - 2.f * d_[c], 0.f);
            if (v0 <= t5A) {
                ull k0 = packnn(v0, j);
                if (k0 < kA[5]) {
                    int pos = 5;
                    while (pos > 0 && k0 < kA[pos - 1]) { kA[pos] = kA[pos - 1]; pos--; }
                    kA[pos] = k0;
                    t5A = __uint_as_float((unsigned)(kA[5] >> 32));
                }
            }
            float v1 = fmaxf(1.f - d_[c] * minv * i_[c], 0.f);
            if (v1 <= t5B) {
                ull k1 = packnn(v1, j);
                if (k1 < kB[5]) {
                    int pos = 5;
                    while (pos > 0 && k1 < kB[pos - 1]) { kB[pos] = kB[pos - 1]; pos--; }
                    kB[pos] = k1;
                    t5B = __uint_as_float((unsigned)(kB[5] >> 32));
                }
            }
        }
    }
    for (int t = 0; t < 6; t++) {
        ull m = kA[0];
#pragma unroll
        for (int off = 16; off; off >>= 1) {
            ull o = __shfl_down_sync(0xffffffffu, m, off);
            if (o < m) m = o;
        }
        m = __shfl_sync(0xffffffffu, m, 0);
        if (kA[0] == m) {
#pragma unroll
            for (int u = 0; u < 5; u++) kA[u] = kA[u + 1];
            kA[5] = SENTK;
        }
        if (lane == 0) smA[wid * 6 + t] = m;
        ull w = kB[0];
#pragma unroll
        for (int off = 16; off; off >>= 1) {
            ull o = __shfl_down_sync(0xffffffffu, w, off);
            if (o < w) w = o;
        }
        w = __shfl_sync(0xffffffffu, w, 0);
        if (kB[0] == w) {
#pragma unroll
            for (int u = 0; u < 5; u++) kB[u] = kB[u + 1];
            kB[5] = SENTK;
        }
        if (lane == 0) smB[wid * 6 + t] = w;
    }
    __syncthreads();
    if (wid < 2) {
        ull* sm = wid ? smB : smA;
        int* outp = (wid ? g_neighA : g_neighCB) + (size_t)s * NT * 5 + row * 5;
        ull k = (lane < 24) ? sm[lane] : ~0ull;
        for (int t = 0; t < 6; t++) {
            ull m = k;
#pragma unroll
            for (int off = 16; off; off >>= 1) {
                ull o = __shfl_down_sync(0xffffffffu, m, off);
                if (o < m) m = o;
            }
            m = __shfl_sync(0xffffffffu, m, 0);
            if (k == m) k = ~0ull;
            if (t > 0 && lane == 0) outp[t - 1] = (int)(m & 0xffffffffu);
        }
    }
}

// ---------------------------------------------------------------------------
// cbneg: UNMASKED top-11 of per-row uniforms (pure threefry, no inputs).
// ---------------------------------------------------------------------------
__global__ void cbneg_kernel(Cfg cfg) {
    __shared__ ull sm[44];
    int row = blockIdx.x, s = blockIdx.y;
    uint32_t k0 = cfg.cbk[s][0], k1 = cfg.cbk[s][1];
    int* neg = g_negCB + ((size_t)s * NT + row) * 11;
    int wid = threadIdx.x >> 5, lane = threadIdx.x & 31;
    ull kk[11];
#pragma unroll
    for (int u = 0; u < 11; u++) kk[u] = ~0ull;
    int jend = wid * 512 + 512;
    for (int j = wid * 512 + lane; j < jend; j += 32) {
        uint32_t bits = tf_bits(k0, k1, (uint32_t)(row * NT + j));
        ull k = ((ull)(0x007fffffu - (bits >> 9)) << 32) | (unsigned)j;
        if (k < kk[10]) {
            int pos = 10;
            while (pos > 0 && k < kk[pos - 1]) { kk[pos] = kk[pos - 1]; pos--; }
            kk[pos] = k;
        }
    }
    for (int t = 0; t < 11; t++) {
        ull m = kk[0];
#pragma unroll
        for (int off = 16; off; off >>= 1) {
            ull o = __shfl_down_sync(0xffffffffu, m, off);
            if (o < m) m = o;
        }
        m = __shfl_sync(0xffffffffu, m, 0);
        if (kk[0] == m) {
#pragma unroll
            for (int u = 0; u < 10; u++) kk[u] = kk[u + 1];
            kk[10] = ~0ull;
        }
        if (lane == 0) sm[wid * 11 + t] = m;
    }
    __syncthreads();
    if (wid == 0) {
        ull ka = (lane < 44) ? sm[lane] : ~0ull;
        ull kb = (lane + 32 < 44) ? sm[lane + 32] : ~0ull;
        for (int t = 0; t < 11; t++) {
            ull loc = ka < kb ? ka : kb;
            ull m = loc;
#pragma unroll
            for (int off = 16; off; off >>= 1) {
                ull o = __shfl_down_sync(0xffffffffu, m, off);
                if (o < m) m = o;
            }
            m = __shfl_sync(0xffffffffu, m, 0);
            if (ka == m) ka = ~0ull;
            else if (kb == m) kb = ~0ull;
            if (lane == 0) neg[t] = (int)(m & 0xffffffffu);
        }
    }
}

// ---------------------------------------------------------------------------
// cbloss: filter top-11 candidates against {row, neigh5}, take first 5, gather.
// ---------------------------------------------------------------------------
__global__ void cbloss_kernel(const float* __restrict__ z1n_,
                              const float* __restrict__ z2n_) {
    int s = blockIdx.y;
    int row = (blockIdx.x * blockDim.x + threadIdx.x) >> 5;
    int lane = threadIdx.x & 31;
    if (row >= NT) return;
    const float* An = (s < 4 ? z2n_ : z1n_) + (size_t)(s & 3) * NT * CD;
    const int* neigh = g_neighCB + (size_t)s * NT * 5;
    const int* cand = g_negCB + ((size_t)s * NT + row) * 11;
    int n[5];
#pragma unroll
    for (int u = 0; u < 5; u++) n[u] = neigh[row * 5 + u];
    int sel[5];
    {
        int c = 0;
#pragma unroll
        for (int k = 0; k < 11; k++) {
            if (c >= 5) break;
            int j = cand[k];
            if (j == row || j == n[0] || j == n[1] || j == n[2] || j == n[3] || j == n[4])
                continue;
            sel[c++] = j;
        }
    }
    float a[24];
    const float* ar = An + (size_t)row * CD;
#pragma unroll
    for (int u = 0; u < 24; u++) a[u] = ar[lane + u * 32];
    float sacc = 0.f;
    for (int k = 0; k < 5; k++) {
        const float* pr = An + (size_t)n[k] * CD;
        const float* nr = An + (size_t)sel[k] * CD;
        float dp = 0.f, dn = 0.f;
#pragma unroll
        for (int u = 0; u < 24; u++) {
            dp += a[u] * pr[lane + u * 32];
            dn += a[u] * nr[lane + u * 32];
        }
#pragma unroll
        for (int off = 16; off; off >>= 1) {
            dp += __shfl_xor_sync(0xffffffffu, dp, off);
            dn += __shfl_xor_sync(0xffffffffu, dn, off);
        }
        float sp = fminf(fmaxf(dp, -1.f), 1.f);
        float sn = fminf(fmaxf(dn, -1.f), 1.f);
        sacc += fmaxf(sn - sp + 0.05f, 0.f);
    }
    if (lane == 0) g_rowCB[s * NT + row] = sacc;
}

// ---------------------------------------------------------------------------
__global__ void mutual_order_kernel(Cfg cfg) {
    __shared__ int matchs[NT];
    __shared__ int cnt[256];
    __shared__ int excl[257];
    int pi = blockIdx.x;
    int u = cfg.pi_uslot[pi], sw = cfg.pi_swap[pi];
    const ull* rm = (sw ? g_colmin : g_rowmin) + (size_t)u * NT;
    const ull* cm = (sw ? g_rowmin : g_colmin) + (size_t)u * NT;
    int* idxB = g_idxB + (size_t)pi * NT;
    int* order = g_order + (size_t)pi * NT;
    int t = threadIdx.x;
    for (int i = t; i < NT; i += 256) matchs[i] = 0;
    __syncthreads();
    int base = t * 8;
#pragma unroll
    for (int uu = 0; uu < 8; uu++) {
        int i = base + uu;
        int b = (int)(rm[i] & 0xffffffffu);
        int v = ((int)(cm[b] & 0xffffffffu) == i) ? b : -1;
        idxB[i] = v;
        if (v >= 0) matchs[v] = 1;
    }
    __syncthreads();
    int m[8]; int c = 0;
#pragma unroll
    for (int uu = 0; uu < 8; uu++) { m[uu] = matchs[base + uu]; c += (m[uu] == 0); }
    cnt[t] = c;
    __syncthreads();
    if (t == 0) {
        int s = 0;
        for (int i = 0; i < 256; i++) { excl[i] = s; s += cnt[i]; }
        excl[256] = s;
    }
    __syncthreads();
    int Utot = excl[256];
    int uo = excl[t];
    int mm = base - uo;
#pragma unroll
    for (int x = 0; x < 8; x++) {
        if (m[x] == 0) order[uo++] = base + x;
        else           order[Utot + mm++] = base + x;
    }
    if (t == 0) g_negc[pi] = (Utot > 0) ? Utot : 1;
}

// ---------------------------------------------------------------------------
__global__ void nrcloss_kernel(const float* __restrict__ z1n_,
                               const float* __restrict__ z2n_, Cfg cfg) {
    int pi = blockIdx.y;
    int i = (blockIdx.x * blockDim.x + threadIdx.x) >> 5;
    int lane = threadIdx.x & 31;
    if (i >= NT) return;
    int side = cfg.pi_side[pi];
    const float* Bn = (side == 0 ? z2n_ : z1n_) + (size_t)cfg.pi_q[pi] * NT * CD;
    const int* idxB = g_idxB + (size_t)pi * NT;
    const int* neighA = g_neighA + (size_t)(side * 4 + cfg.pi_p[pi]) * NT * 5;
    const int* order = g_order + (size_t)pi * NT;
    uint32_t k0 = cfg.kp[pi][0], k1 = cfg.kp[pi][1];
    int ib = idxB[i];
    int uB = ib < 0 ? 0 : ib;
    int nc = g_negc[pi];
    float a[24];
    const float* ar = Bn + (size_t)uB * CD;
#pragma unroll
    for (int u = 0; u < 24; u++) a[u] = ar[lane + u * 32];
    float hs = 0.f; int npos = 0;
    for (int k = 0; k < 5; k++) {
        int pb = idxB[neighA[i * 5 + k]];
        uint32_t bits = tf_bits(k0, k1, 10240u + (uint32_t)(i * 5 + k));
        int nb = order[(int)(bits & 2047u) % nc];
        const float* pr = Bn + (size_t)(pb < 0 ? 0 : pb) * CD;
        const float* nr = Bn + (size_t)nb * CD;
        float dp = 0.f, dn = 0.f;
#pragma unroll
        for (int u = 0; u < 24; u++) {
            dp += a[u] * pr[lane + u * 32];
            dn += a[u] * nr[lane + u * 32];
        }
#pragma unroll
        for (int off = 16; off; off >>= 1) {
            dp += __shfl_xor_sync(0xffffffffu, dp, off);
            dn += __shfl_xor_sync(0xffffffffu, dn, off);
        }
        if (pb >= 0) { hs += fmaxf(dn - dp + 0.4f, 0.f); npos++; }
    }
    if (lane == 0) {
        float per = hs / (float)(npos > 0 ? npos : 1);
        int valid = (ib >= 0) && (npos > 0);
        g_rowNRC[pi * NT + i] = valid ? per : 0.f;
        g_cntNRC[pi * NT + i] = valid ? 1.f : 0.f;
    }
}

// ---------------------------------------------------------------------------
__global__ void reduce_all_kernel() {
    __shared__ float sh[1024];
    int slot = blockIdx.x;
    int t = threadIdx.x;
    const float* buf;
    if (slot < 8) buf = g_rowCB + (size_t)slot * NT;
    else if (slot < 20) buf = g_rowNRC + (size_t)(slot - 8) * NT;
    else buf = g_cntNRC + (size_t)(slot - 20) * NT;
    sh[t] = buf[t] + buf[t + 1024];
    __syncthreads();
    for (int s = 512; s; s >>= 1) {
        if (t < s) sh[t] += sh[t + s];
        __syncthreads();
    }
    if (t == 0) {
        float v = sh[0];
        if (slot < 8) v *= (1.0f / 10240.0f);
        g_slots[slot] = v;
    }
}

__global__ void final_kernel(float* __restrict__ out) {
    float l2 = 0.f;
    for (int i = 0; i < 8; i++) l2 += g_slots[i];
    l2 *= 0.25f;
    float l3 = 0.f;
    for (int s = 0; s < 2; s++) {
        float acc = 0.f;
        for (int j = 0; j < 6; j++) {
            int pi = s * 6 + j;
            float cn = g_slots[20 + pi];
            float sm = g_slots[8 + pi];
            acc += (cn > 0.f) ? sm / fmaxf(cn, 1.f) : 0.f;
        }
        l3 += acc / 6.f;
    }
    out[0] = 10.f * l2 + 10.f * l3;
}

// ---------------------------------------------------------------------------
namespace {
struct HostMT { uint32_t mt[624]; int pos; };
static void mt_seed(HostMT& s, uint32_t seed) {
    for (int p = 0; p < 624; p++) {
        s.mt[p] = seed;
        seed = 1812433253u * (seed ^ (seed >> 30)) + (uint32_t)p + 1u;
    }
    s.pos = 624;
}
static uint32_t mt_next(HostMT& s) {
    if (s.pos == 624) {
        for (int i = 0; i < 624; i++) {
            uint32_t y = (s.mt[i] & 0x80000000u) | (s.mt[(i + 1) % 624] & 0x7fffffffu);
            s.mt[i] = s.mt[(i + 397) % 624] ^ (y >> 1) ^ ((y & 1u) ? 0x9908b0dfu : 0u);
        }
        s.pos = 0;
    }
    uint32_t y = s.mt[s.pos++];
    y ^= y >> 11;
    y ^= (y << 7) & 0x9d2c5680u;
    y ^= (y << 15) & 0xefc60000u;
    y ^= y >> 18;
    return y;
}
static uint32_t mt_interval(HostMT& s, uint32_t mx) {
    if (mx == 0) return 0;
    uint32_t mask = mx;
    mask |= mask >> 1; mask |= mask >> 2; mask |= mask >> 4;
    mask |= mask >> 8; mask |= mask >> 16;
    uint32_t v;
    while ((v = (mt_next(s) & mask)) > mx) {}
    return v;
}
static void perm12(uint32_t seed, int* out) {
    HostMT s; mt_seed(s, seed);
    for (int i = 0; i < 12; i++) out[i] = i;
    for (int i = 11; i > 0; i--) {
        int j = (int)mt_interval(s, (uint32_t)i);
        int t = out[i]; out[i] = out[j]; out[j] = t;
    }
}
}  // namespace

// ---------------------------------------------------------------------------
extern "C" void kernel_launch(void* const* d_in, const int* in_sizes, int n_in,
                              void* d_out, int out_size) {
    const float* z1 = (const float*)d_in[0];
    const float* z2 = (const float*)d_in[1];
    float* out = (float*)d_out;

    float *z1n, *z2n;
    __nv_bfloat16 *rh, *rl, *nh, *nl;
    cudaGetSymbolAddress((void**)&z1n, g_z1n);
    cudaGetSymbolAddress((void**)&z2n, g_z2n);
    cudaGetSymbolAddress((void**)&rh, g_rh);
    cudaGetSymbolAddress((void**)&rl, g_rl);
    cudaGetSymbolAddress((void**)&nh, g_nh);
    cudaGetSymbolAddress((void**)&nl, g_nl);

    Cfg cfg;
    uint32_t ck[4][2];
    for (int i = 0; i < 4; i++)
        threefry2x32(0u, 42u, 0u, (uint32_t)i, ck[i][0], ck[i][1]);
    for (int b = 0; b < 4; b++) {
        threefry2x32(ck[0][0], ck[0][1], 0u, (uint32_t)b, cfg.cbk[b][0], cfg.cbk[b][1]);
        threefry2x32(ck[1][0], ck[1][1], 0u, (uint32_t)b, cfg.cbk[4 + b][0], cfg.cbk[4 + b][1]);
    }
    for (int j = 0; j < 6; j++) {
        threefry2x32(ck[2][0], ck[2][1], 0u, (uint32_t)j, cfg.kp[j][0], cfg.kp[j][1]);
        threefry2x32(ck[3][0], ck[3][1], 0u, (uint32_t)j, cfg.kp[6 + j][0], cfg.kp[6 + j][1]);
    }

    int allp[12][2];
    { int t = 0;
      for (int p = 0; p < 4; p++)
          for (int q = 0; q < 4; q++)
              if (p != q) { allp[t][0] = p; allp[t][1] = q; t++; } }
    int pairs[12][2];
    int perm[12];
    perm12(0u, perm);
    for (int j = 0; j < 6; j++) { pairs[j][0] = allp[perm[j]][0]; pairs[j][1] = allp[perm[j]][1]; }
    perm12(1u, perm);
    for (int j = 0; j < 6; j++) { pairs[6 + j][0] = allp[perm[j]][0]; pairs[6 + j][1] = allp[perm[j]][1]; }

    for (int pi = 0; pi < 12; pi++) {
        cfg.pi_side[pi] = pi / 6;
        cfg.pi_p[pi] = pairs[pi][0];
        cfg.pi_q[pi] = pairs[pi][1];
    }
    int nU = 0;
    bool matched1[12] = {false};
    for (int j0 = 0; j0 < 6; j0++) {
        cfg.u_side[nU] = 0; cfg.u_p[nU] = pairs[j0][0]; cfg.u_q[nU] = pairs[j0][1];
        cfg.pi_uslot[j0] = nU; cfg.pi_swap[j0] = 0;
        for (int j1 = 6; j1 < 12; j1++) {
            if (!matched1[j1] && pairs[j1][0] == pairs[j0][1] && pairs[j1][1] == pairs[j0][0]) {
                cfg.pi_uslot[j1] = nU; cfg.pi_swap[j1] = 1;
                matched1[j1] = true;
                break;
            }
        }
        nU++;
    }
    for (int j1 = 6; j1 < 12; j1++) {
        if (!matched1[j1]) {
            cfg.u_side[nU] = 1; cfg.u_p[nU] = pairs[j1][0]; cfg.u_q[nU] = pairs[j1][1];
            cfg.pi_uslot[j1] = nU; cfg.pi_swap[j1] = 0;
            nU++;
        }
    }
    cfg.nU = nU;

    static cudaStream_t s1 = nullptr;
    static cudaEvent_t evStart = nullptr, evN = nullptr, evCB = nullptr, evJ = nullptr;
    static bool attrSet = false;
    if (!attrSet) {
        cudaFuncSetAttribute(mma_gemm_kernel,
                             cudaFuncAttributeMaxDynamicSharedMemorySize, 2 * STG);
        cudaStreamCreateWithFlags(&s1, cudaStreamNonBlocking);
        cudaEventCreateWithFlags(&evStart, cudaEventDisableTiming);
        cudaEventCreateWithFlags(&evN, cudaEventDisableTiming);
        cudaEventCreateWithFlags(&evCB, cudaEventDisableTiming);
        cudaEventCreateWithFlags(&evJ, cudaEventDisableTiming);
        attrSet = true;
    }

    // Fork immediately: cbneg (pure RNG, no data deps) runs on s1 from t=0,
    // overlapping normalize + self GEMM (tensor) with its ALU work.
    cudaEventRecord(evStart, 0);
    cudaStreamWaitEvent(s1, evStart, 0);
    cbneg_kernel<<<dim3(NT, 8), 128, 0, s1>>>(cfg);
    cudaEventRecord(evCB, s1);

    // Stream 0: normalize + init, record evN for s1's cross GEMM.
    normalize_kernel<<<2048, 256>>>(z1, z2);
    init_kernel<<<48, 1024>>>();
    cudaEventRecord(evN, 0);

    // Branch 1 (s1): cross GEMM + fused argmin -> mutual matching.
    cudaStreamWaitEvent(s1, evN, 0);
    mma_gemm_kernel<<<dim3(16, 16, nU), 256, 2 * STG, s1>>>(rh, rl, nh, nl, 1, cfg);
    mutual_order_kernel<<<12, 256, 0, s1>>>(cfg);
    cudaEventRecord(evJ, s1);

    // Branch 0: self GEMM -> select -> cbloss (filtered negatives).
    mma_gemm_kernel<<<dim3(16, 16, 8), 256, 2 * STG>>>(rh, rl, nh, nl, 0, cfg);
    self_select_kernel<<<dim3(NT, 8), 128>>>();
    cudaStreamWaitEvent(0, evCB, 0);
    cbloss_kernel<<<dim3(256, 8), 256>>>(z1n, z2n);

    // Join, then NRC losses + reductions.
    cudaStreamWaitEvent(0, evJ, 0);
    nrcloss_kernel<<<dim3(256, 12), 256>>>(z1n, z2n, cfg);
    reduce_all_kernel<<<32, 1024>>>();
    final_kernel<<<1, 1>>>(out);
}

// round 17
// speedup vs baseline: 1.0068x; 1.0068x over previous
#include <cuda_runtime.h>
#include <cuda_bf16.h>
#include <cstdint>

#define NT 2048
#define CD 768
#define INFF  __int_as_float(0x7f800000)
#define NINFF __int_as_float(0xff800000)
typedef unsigned long long ull;

// ---------------------------------------------------------------------------
__device__ float g_z1n[4 * NT * CD];
__device__ float g_z2n[4 * NT * CD];
__device__ __nv_bfloat16 g_rh[8 * NT * CD];
__device__ __nv_bfloat16 g_rl[8 * NT * CD];
__device__ __nv_bfloat16 g_nh[8 * NT * CD];
__device__ __nv_bfloat16 g_nl[8 * NT * CD];
__device__ float g_sq[8 * NT];
__device__ float g_inv[8 * NT];
__device__ float g_Sself[8ULL * NT * NT];
__device__ ull   g_rowmin[12 * NT];
__device__ ull   g_colmin[12 * NT];
__device__ int   g_neighCB[8 * NT * 5];
__device__ int   g_negCB[8 * NT * 11];     // unmasked top-11 (rank order)
__device__ int   g_neighA[8 * NT * 5];
__device__ int   g_idxB[12 * NT];
__device__ int   g_order[12 * NT];
__device__ int   g_negc[12];
__device__ float g_rowCB[8 * NT];
__device__ float g_rowNRC[12 * NT];
__device__ float g_cntNRC[12 * NT];
__device__ float g_slots[32];

struct Cfg {
    int nU;
    int u_side[12], u_p[12], u_q[12];
    int pi_uslot[12], pi_swap[12];
    int pi_side[12], pi_p[12], pi_q[12];
    unsigned kp[12][2];
    unsigned cbk[8][2];
};

// ---------------------------------------------------------------------------
__host__ __device__ __forceinline__ void threefry2x32(
    uint32_t k0, uint32_t k1, uint32_t c0, uint32_t c1, uint32_t& o0, uint32_t& o1)
{
    uint32_t ks2 = k0 ^ k1 ^ 0x1BD11BDAu;
    uint32_t x0 = c0 + k0, x1 = c1 + k1;
#define TF_R(r) { x0 += x1; x1 = (x1 << (r)) | (x1 >> (32 - (r))); x1 ^= x0; }
    TF_R(13) TF_R(15) TF_R(26) TF_R(6)
    x0 += k1;  x1 += ks2 + 1u;
    TF_R(17) TF_R(29) TF_R(16) TF_R(24)
    x0 += ks2; x1 += k0 + 2u;
    TF_R(13) TF_R(15) TF_R(26) TF_R(6)
    x0 += k0;  x1 += k1 + 3u;
    TF_R(17) TF_R(29) TF_R(16) TF_R(24)
    x0 += k1;  x1 += ks2 + 4u;
    TF_R(13) TF_R(15) TF_R(26) TF_R(6)
    x0 += ks2; x1 += k0 + 5u;
#undef TF_R
    o0 = x0; o1 = x1;
}
__host__ __device__ __forceinline__ uint32_t tf_bits(uint32_t k0, uint32_t k1, uint32_t idx) {
    uint32_t o0, o1;
    threefry2x32(k0, k1, 0u, idx, o0, o1);
    return o0 ^ o1;
}
__device__ __forceinline__ ull packmin(float v, unsigned idx) {
    unsigned u = __float_as_uint(v);
    u = (u & 0x80000000u) ? ~u : (u | 0x80000000u);
    return ((ull)u << 32) | idx;
}
__device__ __forceinline__ ull packnn(float v, unsigned idx) {
    return ((ull)__float_as_uint(v) << 32) | idx;
}

// ---------------------------------------------------------------------------
__global__ void normalize_kernel(const float* __restrict__ z1,
                                 const float* __restrict__ z2) {
    int gw = (blockIdx.x * blockDim.x + threadIdx.x) >> 5;
    int lane = threadIdx.x & 31;
    if (gw >= 8 * NT) return;
    const float* src;
    float* dst;
    if (gw < 4 * NT) { src = z1 + (size_t)gw * CD; dst = g_z1n + (size_t)gw * CD; }
    else { src = z2 + (size_t)(gw - 4 * NT) * CD; dst = g_z2n + (size_t)(gw - 4 * NT) * CD; }
    __nv_bfloat16* rh = g_rh + (size_t)gw * CD;
    __nv_bfloat16* rl = g_rl + (size_t)gw * CD;
    __nv_bfloat16* nh = g_nh + (size_t)gw * CD;
    __nv_bfloat16* nl = g_nl + (size_t)gw * CD;
    float a[24];
    float s = 0.f;
#pragma unroll
    for (int u = 0; u < 24; u++) { float v = src[lane + u * 32]; a[u] = v; s += v * v; }
#pragma unroll
    for (int off = 16; off; off >>= 1) s += __shfl_xor_sync(0xffffffffu, s, off);
    float inv = rsqrtf(s + 1e-12f);
    if (lane == 0) { g_sq[gw] = s; g_inv[gw] = inv; }
#pragma unroll
    for (int u = 0; u < 24; u++) {
        int c = lane + u * 32;
        float x = a[u];
        __nv_bfloat16 h = __float2bfloat16_rn(x);
        rh[c] = h; rl[c] = __float2bfloat16_rn(x - __bfloat162float(h));
        float xn = x * inv;
        dst[c] = xn;
        __nv_bfloat16 hn = __float2bfloat16_rn(xn);
        nh[c] = hn; nl[c] = __float2bfloat16_rn(xn - __bfloat162float(hn));
    }
}

__global__ void init_kernel() {
    int i = blockIdx.x * blockDim.x + threadIdx.x;
    if (i < 12 * NT) { g_rowmin[i] = ~0ull; g_colmin[i] = ~0ull; }
}

// ---------------------------------------------------------------------------
// bf16x3 HMMA GEMM. mode 0: self, symmetric (skip bx<by, mirror via smem).
// mode 1: cross, fused row/col argmin of (1-dot).
// ---------------------------------------------------------------------------
#define STG 40960
__device__ __forceinline__ void mma16816(float* d, const uint32_t* a, const uint32_t* b) {
    asm volatile(
        "mma.sync.aligned.m16n8k16.row.col.f32.bf16.bf16.f32 "
        "{%0,%1,%2,%3}, {%4,%5,%6,%7}, {%8,%9}, {%0,%1,%2,%3};\n"
        : "+f"(d[0]), "+f"(d[1]), "+f"(d[2]), "+f"(d[3])
        : "r"(a[0]), "r"(a[1]), "r"(a[2]), "r"(a[3]), "r"(b[0]), "r"(b[1]));
}
__device__ __forceinline__ void ldsm4(uint32_t* a, uint32_t p) {
    asm volatile("ldmatrix.sync.aligned.m8n8.x4.shared.b16 {%0,%1,%2,%3}, [%4];\n"
                 : "=r"(a[0]), "=r"(a[1]), "=r"(a[2]), "=r"(a[3]) : "r"(p));
}
__device__ __forceinline__ void cpa16(uint32_t dst, const void* src) {
    asm volatile("cp.async.cg.shared.global [%0], [%1], 16;\n" :: "r"(dst), "l"(src) : "memory");
}

__global__ __launch_bounds__(256, 2) void mma_gemm_kernel(
    const __nv_bfloat16* __restrict__ rh, const __nv_bfloat16* __restrict__ rl,
    const __nv_bfloat16* __restrict__ nh, const __nv_bfloat16* __restrict__ nl,
    int mode, Cfg cfg)
{
    if (mode == 0 && blockIdx.x < blockIdx.y) return;
    extern __shared__ char dsm[];
    uint32_t smb;
    asm("{ .reg .u64 t; cvta.to.shared.u64 t, %1; cvt.u32.u64 %0, t; }" : "=r"(smb) : "l"(dsm));
    int tid = threadIdx.x, wid = tid >> 5, lane = tid & 31;
    int z = blockIdx.z;
    const __nv_bfloat16 *Ah, *Al, *Bh, *Bl;
    if (mode == 0) {
        Ah = rh + (size_t)z * NT * CD; Al = rl + (size_t)z * NT * CD;
        Bh = Ah; Bl = Al;
    } else {
        int sd = cfg.u_side[z];
        size_t po = (size_t)(sd * 4 + cfg.u_p[z]) * NT * CD;
        size_t qo = (size_t)((1 - sd) * 4 + cfg.u_q[z]) * NT * CD;
        Ah = nh + po; Al = nl + po; Bh = nh + qo; Bl = nl + qo;
    }
    int rbase = blockIdx.y * 128, cbase = blockIdx.x * 128;

    auto load_stage = [&](int chunk, int st) {
#pragma unroll
        for (int i = 0; i < 8; i++) {
            int id = tid + i * 256;
            int buf = id >> 9, r = (id >> 2) & 127, seg = id & 3;
            const __nv_bfloat16* gp;
            int grow = (buf < 2 ? rbase : cbase) + r;
            gp = (buf == 0 ? Ah : buf == 1 ? Al : buf == 2 ? Bh : Bl)
                 + (size_t)grow * CD + chunk * 32 + seg * 8;
            cpa16(smb + st * STG + buf * 10240 + r * 80 + seg * 16, gp);
        }
        asm volatile("cp.async.commit_group;\n" ::: "memory");
    };

    float acc[4][4][4];
#pragma unroll
    for (int i = 0; i < 4; i++)
#pragma unroll
        for (int j = 0; j < 4; j++)
#pragma unroll
            for (int k = 0; k < 4; k++) acc[i][j][k] = 0.f;

    int wr = wid >> 2, wc = wid & 3;
    int m0 = wr * 64, n0 = wc * 32;

    load_stage(0, 0);
    for (int c = 0; c < 24; c++) {
        int st = c & 1;
        if (c < 23) {
            load_stage(c + 1, st ^ 1);
            asm volatile("cp.async.wait_group 1;\n" ::: "memory");
        } else {
            asm volatile("cp.async.wait_group 0;\n" ::: "memory");
        }
        __syncthreads();
        uint32_t aH = smb + st * STG, aL = aH + 10240;
#pragma unroll
        for (int ks = 0; ks < 2; ks++) {
            uint32_t arow = (uint32_t)((lane & 15)) * 80 + ks * 32 + ((lane >> 4) << 4);
            uint32_t ah[4][4];
#pragma unroll
            for (int mi = 0; mi < 4; mi++)
                ldsm4(ah[mi], aH + (m0 + mi * 16) * 80 + arow);
            uint32_t boff = (uint32_t)(lane >> 2) * 80 + ks * 32 + ((lane & 3) << 2);
            uint32_t bh[4][2], bl[4][2];
#pragma unroll
            for (int nj = 0; nj < 4; nj++) {
                uint32_t o = (n0 + nj * 8) * 80 + boff;
                bh[nj][0] = *(const uint32_t*)(dsm + st * STG + 20480 + o);
                bh[nj][1] = *(const uint32_t*)(dsm + st * STG + 20480 + o + 16);
                bl[nj][0] = *(const uint32_t*)(dsm + st * STG + 30720 + o);
                bl[nj][1] = *(const uint32_t*)(dsm + st * STG + 30720 + o + 16);
            }
#pragma unroll
            for (int mi = 0; mi < 4; mi++)
#pragma unroll
                for (int nj = 0; nj < 4; nj++) {
                    mma16816(acc[mi][nj], ah[mi], bh[nj]);
                    mma16816(acc[mi][nj], ah[mi], bl[nj]);
                }
            uint32_t al[4][4];
#pragma unroll
            for (int mi = 0; mi < 4; mi++)
                ldsm4(al[mi], aL + (m0 + mi * 16) * 80 + arow);
#pragma unroll
            for (int mi = 0; mi < 4; mi++)
#pragma unroll
                for (int nj = 0; nj < 4; nj++)
                    mma16816(acc[mi][nj], al[mi], bh[nj]);
        }
        __syncthreads();
    }

    if (mode == 0) {
        float* S = g_Sself + (size_t)z * NT * NT;
#pragma unroll
        for (int mi = 0; mi < 4; mi++) {
            int row = rbase + m0 + mi * 16 + (lane >> 2);
#pragma unroll
            for (int nj = 0; nj < 4; nj++) {
                int col = cbase + n0 + nj * 8 + 2 * (lane & 3);
                *(float2*)(S + (size_t)row * NT + col) =
                    make_float2(acc[mi][nj][0], acc[mi][nj][1]);
                *(float2*)(S + (size_t)(row + 8) * NT + col) =
                    make_float2(acc[mi][nj][2], acc[mi][nj][3]);
            }
        }
        if (blockIdx.x != blockIdx.y) {
            float* stage = (float*)dsm;
#pragma unroll
            for (int mi = 0; mi < 4; mi++) {
                int rloc = m0 + mi * 16 + (lane >> 2);
#pragma unroll
                for (int nj = 0; nj < 4; nj++) {
                    int cl = n0 + nj * 8 + 2 * (lane & 3);
                    stage[cl * 132 + rloc] = acc[mi][nj][0];
                    stage[(cl + 1) * 132 + rloc] = acc[mi][nj][1];
                    stage[cl * 132 + rloc + 8] = acc[mi][nj][2];
                    stage[(cl + 1) * 132 + rloc + 8] = acc[mi][nj][3];
                }
            }
            __syncthreads();
            for (int rr = 0; rr < 128; rr += 32) {
                int tr = rr + (tid >> 3);
                int off = (tid & 7) * 4;
#pragma unroll
                for (int k = 0; k < 4; k++)
                    *(float4*)(S + (size_t)(cbase + tr) * NT + rbase + off + k * 32) =
                        *(const float4*)(stage + tr * 132 + off + k * 32);
            }
        }
    } else {
        int u = z;
#pragma unroll
        for (int mi = 0; mi < 4; mi++) {
            int row = rbase + m0 + mi * 16 + (lane >> 2);
            ull r0 = ~0ull, r1 = ~0ull;
#pragma unroll
            for (int nj = 0; nj < 4; nj++) {
                int col = cbase + n0 + nj * 8 + 2 * (lane & 3);
                ull k;
                k = packmin(1.f - acc[mi][nj][0], col);     if (k < r0) r0 = k;
                k = packmin(1.f - acc[mi][nj][1], col + 1); if (k < r0) r0 = k;
                k = packmin(1.f - acc[mi][nj][2], col);     if (k < r1) r1 = k;
                k = packmin(1.f - acc[mi][nj][3], col + 1); if (k < r1) r1 = k;
            }
#pragma unroll
            for (int m = 1; m < 4; m <<= 1) {
                ull o0 = __shfl_xor_sync(0xffffffffu, r0, m);
                ull o1 = __shfl_xor_sync(0xffffffffu, r1, m);
                if (o0 < r0) r0 = o0;
                if (o1 < r1) r1 = o1;
            }
            if ((lane & 3) == 0) {
                atomicMin(&g_rowmin[u * NT + row], r0);
                atomicMin(&g_rowmin[u * NT + row + 8], r1);
            }
        }
#pragma unroll
        for (int nj = 0; nj < 4; nj++) {
            int col = cbase + n0 + nj * 8 + 2 * (lane & 3);
            ull c0 = ~0ull, c1 = ~0ull;
#pragma unroll
            for (int mi = 0; mi < 4; mi++) {
                int row = rbase + m0 + mi * 16 + (lane >> 2);
                ull k;
                k = packmin(1.f - acc[mi][nj][0], row);     if (k < c0) c0 = k;
                k = packmin(1.f - acc[mi][nj][2], row + 8); if (k < c0) c0 = k;
                k = packmin(1.f - acc[mi][nj][1], row);     if (k < c1) c1 = k;
                k = packmin(1.f - acc[mi][nj][3], row + 8); if (k < c1) c1 = k;
            }
#pragma unroll
            for (int m = 4; m < 32; m <<= 1) {
                ull o0 = __shfl_xor_sync(0xffffffffu, c0, m);
                ull o1 = __shfl_xor_sync(0xffffffffu, c1, m);
                if (o0 < c0) c0 = o0;
                if (o1 < c1) c1 = o1;
            }
            if ((lane >> 2) == 0) {
                atomicMin(&g_colmin[u * NT + col], c0);
                atomicMin(&g_colmin[u * NT + col + 1], c1);
            }
        }
    }
}

// ---------------------------------------------------------------------------
// Dual-mode self select with float-threshold hot path.
// ---------------------------------------------------------------------------
#define SENTK (((ull)0x7f800000u << 32) | 0xffffffffu)
__global__ void self_select_kernel() {
    __shared__ ull smA[24], smB[24];
    int row = blockIdx.x, s = blockIdx.y;
    int wid = threadIdx.x >> 5, lane = threadIdx.x & 31;
    const float* sqv = g_sq + (size_t)s * NT;
    const float* invv = g_inv + (size_t)s * NT;
    const float* r = g_Sself + (size_t)s * NT * NT + (size_t)row * NT;
    float msq = sqv[row], minv = invv[row];
    ull kA[6], kB[6];
#pragma unroll
    for (int u = 0; u < 6; u++) { kA[u] = SENTK; kB[u] = SENTK; }
    float t5A = INFF, t5B = INFF;

    float4 dd[4], qq[4], ii[4];
#pragma unroll
    for (int it = 0; it < 4; it++) {
        int j0 = wid * 512 + it * 128 + lane * 4;
        dd[it] = *(const float4*)(r + j0);
        qq[it] = *(const float4*)(sqv + j0);
        ii[it] = *(const float4*)(invv + j0);
    }
#pragma unroll
    for (int it = 0; it < 4; it++) {
        int j0 = wid * 512 + it * 128 + lane * 4;
        float d_[4] = {dd[it].x, dd[it].y, dd[it].z, dd[it].w};
        float q_[4] = {qq[it].x, qq[it].y, qq[it].z, qq[it].w};
        float i_[4] = {ii[it].x, ii[it].y, ii[it].z, ii[it].w};
#pragma unroll
        for (int c = 0; c < 4; c++) {
            unsigned j = j0 + c;
            float v0 = fmaxf(msq + q_[c] - 2.f * d_[c], 0.f);
            if (v0 <= t5A) {
                ull k0 = packnn(v0, j);
                if (k0 < kA[5]) {
                    int pos = 5;
                    while (pos > 0 && k0 < kA[pos - 1]) { kA[pos] = kA[pos - 1]; pos--; }
                    kA[pos] = k0;
                    t5A = __uint_as_float((unsigned)(kA[5] >> 32));
                }
            }
            float v1 = fmaxf(1.f - d_[c] * minv * i_[c], 0.f);
            if (v1 <= t5B) {
                ull k1 = packnn(v1, j);
                if (k1 < kB[5]) {
                    int pos = 5;
                    while (pos > 0 && k1 < kB[pos - 1]) { kB[pos] = kB[pos - 1]; pos--; }
                    kB[pos] = k1;
                    t5B = __uint_as_float((unsigned)(kB[5] >> 32));
                }
            }
        }
    }
    for (int t = 0; t < 6; t++) {
        ull m = kA[0];
#pragma unroll
        for (int off = 16; off; off >>= 1) {
            ull o = __shfl_down_sync(0xffffffffu, m, off);
            if (o < m) m = o;
        }
        m = __shfl_sync(0xffffffffu, m, 0);
        if (kA[0] == m) {
#pragma unroll
            for (int u = 0; u < 5; u++) kA[u] = kA[u + 1];
            kA[5] = SENTK;
        }
        if (lane == 0) smA[wid * 6 + t] = m;
        ull w = kB[0];
#pragma unroll
        for (int off = 16; off; off >>= 1) {
            ull o = __shfl_down_sync(0xffffffffu, w, off);
            if (o < w) w = o;
        }
        w = __shfl_sync(0xffffffffu, w, 0);
        if (kB[0] == w) {
#pragma unroll
            for (int u = 0; u < 5; u++) kB[u] = kB[u + 1];
            kB[5] = SENTK;
        }
        if (lane == 0) smB[wid * 6 + t] = w;
    }
    __syncthreads();
    if (wid < 2) {
        ull* sm = wid ? smB : smA;
        int* outp = (wid ? g_neighA : g_neighCB) + (size_t)s * NT * 5 + row * 5;
        ull k = (lane < 24) ? sm[lane] : ~0ull;
        for (int t = 0; t < 6; t++) {
            ull m = k;
#pragma unroll
            for (int off = 16; off; off >>= 1) {
                ull o = __shfl_down_sync(0xffffffffu, m, off);
                if (o < m) m = o;
            }
            m = __shfl_sync(0xffffffffu, m, 0);
            if (k == m) k = ~0ull;
            if (t > 0 && lane == 0) outp[t - 1] = (int)(m & 0xffffffffu);
        }
    }
}

// ---------------------------------------------------------------------------
// cbneg: UNMASKED top-11 of per-row uniforms (pure threefry, no inputs).
// ---------------------------------------------------------------------------
__global__ void cbneg_kernel(Cfg cfg) {
    __shared__ ull sm[44];
    int row = blockIdx.x, s = blockIdx.y;
    uint32_t k0 = cfg.cbk[s][0], k1 = cfg.cbk[s][1];
    int* neg = g_negCB + ((size_t)s * NT + row) * 11;
    int wid = threadIdx.x >> 5, lane = threadIdx.x & 31;
    ull kk[11];
#pragma unroll
    for (int u = 0; u < 11; u++) kk[u] = ~0ull;
    int jend = wid * 512 + 512;
    for (int j = wid * 512 + lane; j < jend; j += 32) {
        uint32_t bits = tf_bits(k0, k1, (uint32_t)(row * NT + j));
        ull k = ((ull)(0x007fffffu - (bits >> 9)) << 32) | (unsigned)j;
        if (k < kk[10]) {
            int pos = 10;
            while (pos > 0 && k < kk[pos - 1]) { kk[pos] = kk[pos - 1]; pos--; }
            kk[pos] = k;
        }
    }
    for (int t = 0; t < 11; t++) {
        ull m = kk[0];
#pragma unroll
        for (int off = 16; off; off >>= 1) {
            ull o = __shfl_down_sync(0xffffffffu, m, off);
            if (o < m) m = o;
        }
        m = __shfl_sync(0xffffffffu, m, 0);
        if (kk[0] == m) {
#pragma unroll
            for (int u = 0; u < 10; u++) kk[u] = kk[u + 1];
            kk[10] = ~0ull;
        }
        if (lane == 0) sm[wid * 11 + t] = m;
    }
    __syncthreads();
    if (wid == 0) {
        ull ka = (lane < 44) ? sm[lane] : ~0ull;
        ull kb = (lane + 32 < 44) ? sm[lane + 32] : ~0ull;
        for (int t = 0; t < 11; t++) {
            ull loc = ka < kb ? ka : kb;
            ull m = loc;
#pragma unroll
            for (int off = 16; off; off >>= 1) {
                ull o = __shfl_down_sync(0xffffffffu, m, off);
                if (o < m) m = o;
            }
            m = __shfl_sync(0xffffffffu, m, 0);
            if (ka == m) ka = ~0ull;
            else if (kb == m) kb = ~0ull;
            if (lane == 0) neg[t] = (int)(m & 0xffffffffu);
        }
    }
}

// ---------------------------------------------------------------------------
// cbloss: filter top-11 candidates against {row, neigh5}, take first 5, gather.
// ---------------------------------------------------------------------------
__global__ void cbloss_kernel(const float* __restrict__ z1n_,
                              const float* __restrict__ z2n_) {
    int s = blockIdx.y;
    int row = (blockIdx.x * blockDim.x + threadIdx.x) >> 5;
    int lane = threadIdx.x & 31;
    if (row >= NT) return;
    const float* An = (s < 4 ? z2n_ : z1n_) + (size_t)(s & 3) * NT * CD;
    const int* neigh = g_neighCB + (size_t)s * NT * 5;
    const int* cand = g_negCB + ((size_t)s * NT + row) * 11;
    int n[5];
#pragma unroll
    for (int u = 0; u < 5; u++) n[u] = neigh[row * 5 + u];
    int sel[5];
    {
        int c = 0;
#pragma unroll
        for (int k = 0; k < 11; k++) {
            if (c >= 5) break;
            int j = cand[k];
            if (j == row || j == n[0] || j == n[1] || j == n[2] || j == n[3] || j == n[4])
                continue;
            sel[c++] = j;
        }
    }
    float a[24];
    const float* ar = An + (size_t)row * CD;
#pragma unroll
    for (int u = 0; u < 24; u++) a[u] = ar[lane + u * 32];
    float sacc = 0.f;
    for (int k = 0; k < 5; k++) {
        const float* pr = An + (size_t)n[k] * CD;
        const float* nr = An + (size_t)sel[k] * CD;
        float dp = 0.f, dn = 0.f;
#pragma unroll
        for (int u = 0; u < 24; u++) {
            dp += a[u] * pr[lane + u * 32];
            dn += a[u] * nr[lane + u * 32];
        }
#pragma unroll
        for (int off = 16; off; off >>= 1) {
            dp += __shfl_xor_sync(0xffffffffu, dp, off);
            dn += __shfl_xor_sync(0xffffffffu, dn, off);
        }
        float sp = fminf(fmaxf(dp, -1.f), 1.f);
        float sn = fminf(fmaxf(dn, -1.f), 1.f);
        sacc += fmaxf(sn - sp + 0.05f, 0.f);
    }
    if (lane == 0) g_rowCB[s * NT + row] = sacc;
}

// ---------------------------------------------------------------------------
__global__ void mutual_order_kernel(Cfg cfg) {
    __shared__ int matchs[NT];
    __shared__ int cnt[256];
    __shared__ int excl[257];
    int pi = blockIdx.x;
    int u = cfg.pi_uslot[pi], sw = cfg.pi_swap[pi];
    const ull* rm = (sw ? g_colmin : g_rowmin) + (size_t)u * NT;
    const ull* cm = (sw ? g_rowmin : g_colmin) + (size_t)u * NT;
    int* idxB = g_idxB + (size_t)pi * NT;
    int* order = g_order + (size_t)pi * NT;
    int t = threadIdx.x;
    for (int i = t; i < NT; i += 256) matchs[i] = 0;
    __syncthreads();
    int base = t * 8;
#pragma unroll
    for (int uu = 0; uu < 8; uu++) {
        int i = base + uu;
        int b = (int)(rm[i] & 0xffffffffu);
        int v = ((int)(cm[b] & 0xffffffffu) == i) ? b : -1;
        idxB[i] = v;
        if (v >= 0) matchs[v] = 1;
    }
    __syncthreads();
    int m[8]; int c = 0;
#pragma unroll
    for (int uu = 0; uu < 8; uu++) { m[uu] = matchs[base + uu]; c += (m[uu] == 0); }
    cnt[t] = c;
    __syncthreads();
    if (t == 0) {
        int s = 0;
        for (int i = 0; i < 256; i++) { excl[i] = s; s += cnt[i]; }
        excl[256] = s;
    }
    __syncthreads();
    int Utot = excl[256];
    int uo = excl[t];
    int mm = base - uo;
#pragma unroll
    for (int x = 0; x < 8; x++) {
        if (m[x] == 0) order[uo++] = base + x;
        else           order[Utot + mm++] = base + x;
    }
    if (t == 0) g_negc[pi] = (Utot > 0) ? Utot : 1;
}

// ---------------------------------------------------------------------------
__global__ void nrcloss_kernel(const float* __restrict__ z1n_,
                               const float* __restrict__ z2n_, Cfg cfg) {
    int pi = blockIdx.y;
    int i = (blockIdx.x * blockDim.x + threadIdx.x) >> 5;
    int lane = threadIdx.x & 31;
    if (i >= NT) return;
    int side = cfg.pi_side[pi];
    const float* Bn = (side == 0 ? z2n_ : z1n_) + (size_t)cfg.pi_q[pi] * NT * CD;
    const int* idxB = g_idxB + (size_t)pi * NT;
    const int* neighA = g_neighA + (size_t)(side * 4 + cfg.pi_p[pi]) * NT * 5;
    const int* order = g_order + (size_t)pi * NT;
    uint32_t k0 = cfg.kp[pi][0], k1 = cfg.kp[pi][1];
    int ib = idxB[i];
    int uB = ib < 0 ? 0 : ib;
    int nc = g_negc[pi];
    float a[24];
    const float* ar = Bn + (size_t)uB * CD;
#pragma unroll
    for (int u = 0; u < 24; u++) a[u] = ar[lane + u * 32];
    float hs = 0.f; int npos = 0;
    for (int k = 0; k < 5; k++) {
        int pb = idxB[neighA[i * 5 + k]];
        uint32_t bits = tf_bits(k0, k1, 10240u + (uint32_t)(i * 5 + k));
        int nb = order[(int)(bits & 2047u) % nc];
        const float* pr = Bn + (size_t)(pb < 0 ? 0 : pb) * CD;
        const float* nr = Bn + (size_t)nb * CD;
        float dp = 0.f, dn = 0.f;
#pragma unroll
        for (int u = 0; u < 24; u++) {
            dp += a[u] * pr[lane + u * 32];
            dn += a[u] * nr[lane + u * 32];
        }
#pragma unroll
        for (int off = 16; off; off >>= 1) {
            dp += __shfl_xor_sync(0xffffffffu, dp, off);
            dn += __shfl_xor_sync(0xffffffffu, dn, off);
        }
        if (pb >= 0) { hs += fmaxf(dn - dp + 0.4f, 0.f); npos++; }
    }
    if (lane == 0) {
        float per = hs / (float)(npos > 0 ? npos : 1);
        int valid = (ib >= 0) && (npos > 0);
        g_rowNRC[pi * NT + i] = valid ? per : 0.f;
        g_cntNRC[pi * NT + i] = valid ? 1.f : 0.f;
    }
}

// ---------------------------------------------------------------------------
__global__ void reduce_all_kernel() {
    __shared__ float sh[1024];
    int slot = blockIdx.x;
    int t = threadIdx.x;
    const float* buf;
    if (slot < 8) buf = g_rowCB + (size_t)slot * NT;
    else if (slot < 20) buf = g_rowNRC + (size_t)(slot - 8) * NT;
    else buf = g_cntNRC + (size_t)(slot - 20) * NT;
    sh[t] = buf[t] + buf[t + 1024];
    __syncthreads();
    for (int s = 512; s; s >>= 1) {
        if (t < s) sh[t] += sh[t + s];
        __syncthreads();
    }
    if (t == 0) {
        float v = sh[0];
        if (slot < 8) v *= (1.0f / 10240.0f);
        g_slots[slot] = v;
    }
}

__global__ void final_kernel(float* __restrict__ out) {
    float l2 = 0.f;
    for (int i = 0; i < 8; i++) l2 += g_slots[i];
    l2 *= 0.25f;
    float l3 = 0.f;
    for (int s = 0; s < 2; s++) {
        float acc = 0.f;
        for (int j = 0; j < 6; j++) {
            int pi = s * 6 + j;
            float cn = g_slots[20 + pi];
            float sm = g_slots[8 + pi];
            acc += (cn > 0.f) ? sm / fmaxf(cn, 1.f) : 0.f;
        }
        l3 += acc / 6.f;
    }
    out[0] = 10.f * l2 + 10.f * l3;
}

// ---------------------------------------------------------------------------
namespace {
struct HostMT { uint32_t mt[624]; int pos; };
static void mt_seed(HostMT& s, uint32_t seed) {
    for (int p = 0; p < 624; p++) {
        s.mt[p] = seed;
        seed = 1812433253u * (seed ^ (seed >> 30)) + (uint32_t)p + 1u;
    }
    s.pos = 624;
}
static uint32_t mt_next(HostMT& s) {
    if (s.pos == 624) {
        for (int i = 0; i < 624; i++) {
            uint32_t y = (s.mt[i] & 0x80000000u) | (s.mt[(i + 1) % 624] & 0x7fffffffu);
            s.mt[i] = s.mt[(i + 397) % 624] ^ (y >> 1) ^ ((y & 1u) ? 0x9908b0dfu : 0u);
        }
        s.pos = 0;
    }
    uint32_t y = s.mt[s.pos++];
    y ^= y >> 11;
    y ^= (y << 7) & 0x9d2c5680u;
    y ^= (y << 15) & 0xefc60000u;
    y ^= y >> 18;
    return y;
}
static uint32_t mt_interval(HostMT& s, uint32_t mx) {
    if (mx == 0) return 0;
    uint32_t mask = mx;
    mask |= mask >> 1; mask |= mask >> 2; mask |= mask >> 4;
    mask |= mask >> 8; mask |= mask >> 16;
    uint32_t v;
    while ((v = (mt_next(s) & mask)) > mx) {}
    return v;
}
static void perm12(uint32_t seed, int* out) {
    HostMT s; mt_seed(s, seed);
    for (int i = 0; i < 12; i++) out[i] = i;
    for (int i = 11; i > 0; i--) {
        int j = (int)mt_interval(s, (uint32_t)i);
        int t = out[i]; out[i] = out[j]; out[j] = t;
    }
}
}  // namespace

// ---------------------------------------------------------------------------
extern "C" void kernel_launch(void* const* d_in, const int* in_sizes, int n_in,
                              void* d_out, int out_size) {
    const float* z1 = (const float*)d_in[0];
    const float* z2 = (const float*)d_in[1];
    float* out = (float*)d_out;

    float *z1n, *z2n;
    __nv_bfloat16 *rh, *rl, *nh, *nl;
    cudaGetSymbolAddress((void**)&z1n, g_z1n);
    cudaGetSymbolAddress((void**)&z2n, g_z2n);
    cudaGetSymbolAddress((void**)&rh, g_rh);
    cudaGetSymbolAddress((void**)&rl, g_rl);
    cudaGetSymbolAddress((void**)&nh, g_nh);
    cudaGetSymbolAddress((void**)&nl, g_nl);

    Cfg cfg;
    uint32_t ck[4][2];
    for (int i = 0; i < 4; i++)
        threefry2x32(0u, 42u, 0u, (uint32_t)i, ck[i][0], ck[i][1]);
    for (int b = 0; b < 4; b++) {
        threefry2x32(ck[0][0], ck[0][1], 0u, (uint32_t)b, cfg.cbk[b][0], cfg.cbk[b][1]);
        threefry2x32(ck[1][0], ck[1][1], 0u, (uint32_t)b, cfg.cbk[4 + b][0], cfg.cbk[4 + b][1]);
    }
    for (int j = 0; j < 6; j++) {
        threefry2x32(ck[2][0], ck[2][1], 0u, (uint32_t)j, cfg.kp[j][0], cfg.kp[j][1]);
        threefry2x32(ck[3][0], ck[3][1], 0u, (uint32_t)j, cfg.kp[6 + j][0], cfg.kp[6 + j][1]);
    }

    int allp[12][2];
    { int t = 0;
      for (int p = 0; p < 4; p++)
          for (int q = 0; q < 4; q++)
              if (p != q) { allp[t][0] = p; allp[t][1] = q; t++; } }
    int pairs[12][2];
    int perm[12];
    perm12(0u, perm);
    for (int j = 0; j < 6; j++) { pairs[j][0] = allp[perm[j]][0]; pairs[j][1] = allp[perm[j]][1]; }
    perm12(1u, perm);
    for (int j = 0; j < 6; j++) { pairs[6 + j][0] = allp[perm[j]][0]; pairs[6 + j][1] = allp[perm[j]][1]; }

    for (int pi = 0; pi < 12; pi++) {
        cfg.pi_side[pi] = pi / 6;
        cfg.pi_p[pi] = pairs[pi][0];
        cfg.pi_q[pi] = pairs[pi][1];
    }
    int nU = 0;
    bool matched1[12] = {false};
    for (int j0 = 0; j0 < 6; j0++) {
        cfg.u_side[nU] = 0; cfg.u_p[nU] = pairs[j0][0]; cfg.u_q[nU] = pairs[j0][1];
        cfg.pi_uslot[j0] = nU; cfg.pi_swap[j0] = 0;
        for (int j1 = 6; j1 < 12; j1++) {
            if (!matched1[j1] && pairs[j1][0] == pairs[j0][1] && pairs[j1][1] == pairs[j0][0]) {
                cfg.pi_uslot[j1] = nU; cfg.pi_swap[j1] = 1;
                matched1[j1] = true;
                break;
            }
        }
        nU++;
    }
    for (int j1 = 6; j1 < 12; j1++) {
        if (!matched1[j1]) {
            cfg.u_side[nU] = 1; cfg.u_p[nU] = pairs[j1][0]; cfg.u_q[nU] = pairs[j1][1];
            cfg.pi_uslot[j1] = nU; cfg.pi_swap[j1] = 0;
            nU++;
        }
    }
    cfg.nU = nU;

    static cudaStream_t s1 = nullptr, s2 = nullptr;
    static cudaEvent_t evStart = nullptr, evS = nullptr, evCB = nullptr, evJ = nullptr;
    static bool attrSet = false;
    if (!attrSet) {
        cudaFuncSetAttribute(mma_gemm_kernel,
                             cudaFuncAttributeMaxDynamicSharedMemorySize, 2 * STG);
        cudaStreamCreateWithFlags(&s1, cudaStreamNonBlocking);
        cudaStreamCreateWithFlags(&s2, cudaStreamNonBlocking);
        cudaEventCreateWithFlags(&evStart, cudaEventDisableTiming);
        cudaEventCreateWithFlags(&evS, cudaEventDisableTiming);
        cudaEventCreateWithFlags(&evCB, cudaEventDisableTiming);
        cudaEventCreateWithFlags(&evJ, cudaEventDisableTiming);
        attrSet = true;
    }

    // s2 (from root): cbneg top-11 — pure RNG, overlaps normalize + self GEMM.
    cudaEventRecord(evStart, 0);
    cudaStreamWaitEvent(s2, evStart, 0);
    cbneg_kernel<<<dim3(NT, 8), 128, 0, s2>>>(cfg);
    cudaEventRecord(evCB, s2);

    // s0: normalize + init + self GEMM.  Fork for cross GEMM AFTER self GEMM
    // (R13-proven placement: tensor-bound cross overlaps ALU-bound selects).
    normalize_kernel<<<2048, 256>>>(z1, z2);
    init_kernel<<<48, 1024>>>();
    mma_gemm_kernel<<<dim3(16, 16, 8), 256, 2 * STG>>>(rh, rl, nh, nl, 0, cfg);
    cudaEventRecord(evS, 0);
    cudaStreamWaitEvent(s1, evS, 0);

    // s1: cross GEMM + fused argmin -> mutual matching.
    mma_gemm_kernel<<<dim3(16, 16, nU), 256, 2 * STG, s1>>>(rh, rl, nh, nl, 1, cfg);
    mutual_order_kernel<<<12, 256, 0, s1>>>(cfg);
    cudaEventRecord(evJ, s1);

    // s0: select -> cbloss (overlaps s1's cross GEMM).
    self_select_kernel<<<dim3(NT, 8), 128>>>();
    cudaStreamWaitEvent(0, evCB, 0);
    cbloss_kernel<<<dim3(256, 8), 256>>>(z1n, z2n);

    // Join, then NRC losses + reductions.
    cudaStreamWaitEvent(0, evJ, 0);
    nrcloss_kernel<<<dim3(256, 12), 256>>>(z1n, z2n, cfg);
    reduce_all_kernel<<<32, 1024>>>();
    final_kernel<<<1, 1>>>(out);
}